// round 6
// baseline (speedup 1.0000x reference)
#include <cuda_runtime.h>

#define Bn  2
#define CO  8
#define CI  8
#define DD  8
#define GH  16
#define GW  16
#define HH  512
#define WW  512
#define TW  256        // threads per block = tile width in pixels
#define THR 4          // tile height (rows)
#define CHR 2          // rows per phase chunk
#define NY  3
#define NX  10
#define CSTR 132       // floats per (r,xx) cell in gy

#define BSTR 520       // float2 per d-plane (512 px + pad)
#define GY_FLOATS   (THR * NX * CSTR)                  // 5280
#define SG_FLOATS   (NY * NX * 2 * DD * CO)            // 3840
#define SMEM_BYTES  (GY_FLOATS * 4 + DD * BSTR * 8)    // 21120 + 33280 = 54400 B

typedef unsigned long long ull;

__device__ __forceinline__ ull ffma2(ull a, ull b, ull c) {
    ull d;
    asm("fma.rn.f32x2 %0, %1, %2, %3;" : "=l"(d) : "l"(a), "l"(b), "l"(c));
    return d;
}
__device__ __forceinline__ ull pack2(float lo, float hi) {
    ull r;
    asm("mov.b64 %0, {%1, %2};" : "=l"(r) : "f"(lo), "f"(hi));
    return r;
}
__device__ __forceinline__ float2 unpack2(ull v) {
    float2 f;
    asm("mov.b64 {%0, %1}, %2;" : "=f"(f.x), "=f"(f.y) : "l"(v));
    return f;
}

__global__ __launch_bounds__(TW, 3) void bsa_kernel(
    const float* __restrict__ grid,
    const float* __restrict__ guide,
    const float* __restrict__ inp,
    float* __restrict__ out)
{
    extern __shared__ __align__(16) float sm[];
    float*  gy  = sm;                                         // y-folded coeffs
    float*  sg  = sm + GY_FLOATS;                             // raw grid (temp)
    float2* bsp = reinterpret_cast<float2*>(sm + GY_FLOATS);  // basis (aliases sg)

    const int b  = blockIdx.z;
    const int w0 = blockIdx.x * TW;
    const int h0 = blockIdx.y * THR;
    const int t  = threadIdx.x;
    const float s = 15.0f / 511.0f;

    int ybase = (int)((float)h0 * s); if (ybase > GH - 2) ybase = GH - 2;
    int xbase = (int)((float)w0 * s); if (xbase > GW - 2) xbase = GW - 2;

    // ---- stage raw grid slice ----
    const float* gptr0 = grid + (size_t)b * (CO * 2 * DD * GH * GW);
    #pragma unroll
    for (int i = t; i < SG_FLOATS; i += TW) {
        int xx = i % NX;
        int r  = i / NX;
        int yy = r % NY;  r /= NY;
        int d  = r % DD;  r /= DD;
        int k  = r % 2;
        int co = r / 2;
        int gyy = ybase + yy; if (gyy > GH - 1) gyy = GH - 1;
        int gx  = xbase + xx; if (gx  > GW - 1) gx  = GW - 1;
        sg[(((yy * NX + xx) * 2 + k) * DD + d) * CO + co] =
            gptr0[(((co * 2 + k) * DD + d) * GH + gyy) * GW + gx];
    }
    __syncthreads();

    // ---- y-fold into gy; fold 1/8 bias mean into k==1 coefficients ----
    #pragma unroll
    for (int j = t; j < THR * NX * DD * 16; j += TW) {
        int co = j & 7;
        int k  = (j >> 3) & 1;
        int d  = (j >> 4) & 7;
        int v  = j >> 7;           // r*NX + xx
        int xx = v % NX;
        int r  = v / NX;
        float yp = (float)(h0 + r) * s;
        int   y0 = (int)yp; if (y0 > GH - 2) y0 = GH - 2;
        float wy = yp - (float)y0;
        int   ly = y0 - ybase;
        float v0 = sg[(((ly       * NX + xx) * 2 + k) * DD + d) * CO + co];
        float v1 = sg[((((ly + 1) * NX + xx) * 2 + k) * DD + d) * CO + co];
        float val = v0 + wy * (v1 - v0);
        val *= (k ? 0.125f : 1.0f);
        gy[(r * NX + xx) * CSTR + d * 16 + k * 8 + co] = val;
    }

    // ---- phase-2 per-thread geometry (chunk-invariant) ----
    const int coh  = t >> 7;          // 0: co 0-3, 1: co 4-7
    const int rem  = t & 127;
    const int rl   = rem >> 6;        // row within chunk
    const int gcol = (rem & 63) << 2; // start column within tile

    float u[3][4];
    int x00 = 0;
    #pragma unroll
    for (int j = 0; j < 4; j++) {
        float xp = (float)(w0 + gcol + j) * s;
        int   x0 = (int)xp; if (x0 > GW - 2) x0 = GW - 2;
        float wx = xp - (float)x0;
        if (j == 0) x00 = x0;
        int c = x0 - x00;             // 0 or 1
        u[0][j] = (c == 0) ? (1.0f - wx) : 0.0f;
        u[1][j] = (c == 0) ? wx          : (1.0f - wx);
        u[2][j] = (c == 0) ? 0.0f        : wx;
    }
    const int lx0 = x00 - xbase;

    const size_t hw = (size_t)HH * WW;
    const float* gup  = guide + (size_t)b * CI * hw + (size_t)h0 * WW + w0 + t;
    const float* inpp = inp   + (size_t)b * CI * hw + (size_t)h0 * WW + w0 + t;

    #pragma unroll
    for (int ch = 0; ch < THR / CHR; ch++) {
        __syncthreads();   // bs free (covers sg alias on first iter, p2 reads after)

        // ---- phase 1: z-basis scatter-accumulate for rows {2ch, 2ch+1} ----
        #pragma unroll
        for (int rr = 0; rr < CHR; rr++) {
            const int row = ch * CHR + rr;
            float2* col = bsp + (rr * TW + t);
            #pragma unroll
            for (int d = 0; d < DD; d++) col[d * BSTR] = make_float2(0.f, 0.f);

            #pragma unroll
            for (int ci = 0; ci < CI; ci++) {
                float g = gup [ci * hw + (size_t)row * WW];
                float v = inpp[ci * hw + (size_t)row * WW];
                float zp = fminf(fmaxf(g * 7.0f, 0.0f), 7.0f);
                int d0 = (int)zp; if (d0 > 6) d0 = 6;
                float f  = zp - (float)d0;
                float vf = v * f;
                float v1 = v - vf;
                float f1 = 1.0f - f;
                float2* p = col + d0 * BSTR;
                float2 a0 = p[0];
                a0.x += v1; a0.y += f1;
                p[0] = a0;
                float2 a1 = p[BSTR];
                a1.x += vf; a1.y += f;
                p[BSTR] = a1;
            }
        }
        __syncthreads();

        // ---- phase 2: 4 px x 4 co per thread ----
        const int row = ch * CHR + rl;
        const float* cell0 = gy + (row * NX + lx0) * CSTR;
        const int bbase = rl * TW + gcol;   // float2 index within plane

        ull acc[4][2];
        #pragma unroll
        for (int j = 0; j < 4; j++) { acc[j][0] = 0ull; acc[j][1] = 0ull; }

        #pragma unroll
        for (int d = 0; d < DD; d++) {
            const float4* q = reinterpret_cast<const float4*>(bsp + d * BSTR + bbase);
            float4 qa = q[0];   // (A0,B0,A1,B1)
            float4 qb = q[1];   // (A2,B2,A3,B3)
            float Aj[4] = {qa.x, qa.z, qb.x, qb.z};
            float Bj[4] = {qa.y, qa.w, qb.y, qb.w};

            #pragma unroll
            for (int c = 0; c < 3; c++) {
                const float* cp = cell0 + c * CSTR + d * 16 + coh * 4;
                ulonglong2 wq = *reinterpret_cast<const ulonglong2*>(cp);      // W co-quad
                ulonglong2 bq = *reinterpret_cast<const ulonglong2*>(cp + 8);  // B co-quad
                #pragma unroll
                for (int j = 0; j < 4; j++) {
                    float uu = u[c][j];
                    float au = Aj[j] * uu;
                    float bu = Bj[j] * uu;
                    ull AU = pack2(au, au);
                    ull BU = pack2(bu, bu);
                    acc[j][0] = ffma2(wq.x, AU, acc[j][0]);
                    acc[j][1] = ffma2(wq.y, AU, acc[j][1]);
                    acc[j][0] = ffma2(bq.x, BU, acc[j][0]);
                    acc[j][1] = ffma2(bq.y, BU, acc[j][1]);
                }
            }
        }

        // ---- epilogue: 4 co planes, STG.128 of 4 px each ----
        float vals[4][4];   // [px][co-in-quad]
        #pragma unroll
        for (int j = 0; j < 4; j++) {
            float2 f0 = unpack2(acc[j][0]);
            float2 f1 = unpack2(acc[j][1]);
            vals[j][0] = f0.x; vals[j][1] = f0.y;
            vals[j][2] = f1.x; vals[j][3] = f1.y;
        }
        float* op = out + (size_t)b * CO * hw + (size_t)(h0 + row) * WW + w0 + gcol;
        #pragma unroll
        for (int cq = 0; cq < 4; cq++) {
            int co = coh * 4 + cq;
            float4 qv = make_float4(vals[0][cq], vals[1][cq], vals[2][cq], vals[3][cq]);
            *reinterpret_cast<float4*>(op + (size_t)co * hw) = qv;
        }
    }
}

extern "C" void kernel_launch(void* const* d_in, const int* in_sizes, int n_in,
                              void* d_out, int out_size) {
    const float* grid  = (const float*)d_in[0];   // (2,8,2,8,16,16)
    const float* guide = (const float*)d_in[1];   // (2,8,512,512)
    const float* inp   = (const float*)d_in[2];   // (2,8,512,512)
    float* out = (float*)d_out;                   // (2,8,512,512)

    cudaFuncSetAttribute(bsa_kernel,
                         cudaFuncAttributeMaxDynamicSharedMemorySize, SMEM_BYTES);

    dim3 gdim(WW / TW, HH / THR, Bn);   // (2, 128, 2) = 512 blocks
    bsa_kernel<<<gdim, TW, SMEM_BYTES>>>(grid, guide, inp, out);
}

// round 7
// speedup vs baseline: 1.0525x; 1.0525x over previous
#include <cuda_runtime.h>

#define Bn  2
#define CO  8
#define CI  8
#define DD  8
#define GH  16
#define GW  16
#define HH  512
#define WW  512
#define TW  256        // threads per block = tile width in pixels
#define THR 4          // tile height (rows)
#define NY  3
#define NX  10
#define CSTR 132       // floats per (r,xx) cell in gy

#define PSTR 1152      // float4 per d-pair plane (1024 px + 128 pad)
#define GY_FLOATS   (THR * NX * CSTR)                  // 5280
#define SG_FLOATS   (NY * NX * 2 * DD * CO)            // 3840
#define SMEM_BYTES  (GY_FLOATS * 4 + 4 * PSTR * 16)    // 21120 + 73728 = 94848

typedef unsigned long long ull;

__device__ __forceinline__ ull ffma2(ull a, ull b, ull c) {
    ull d;
    asm("fma.rn.f32x2 %0, %1, %2, %3;" : "=l"(d) : "l"(a), "l"(b), "l"(c));
    return d;
}
__device__ __forceinline__ ull fmul2(ull a, ull b) {
    ull d;
    asm("mul.rn.f32x2 %0, %1, %2;" : "=l"(d) : "l"(a), "l"(b));
    return d;
}
__device__ __forceinline__ ull fadd2(ull a, ull b) {
    ull d;
    asm("add.rn.f32x2 %0, %1, %2;" : "=l"(d) : "l"(a), "l"(b));
    return d;
}
__device__ __forceinline__ ull pack2(float lo, float hi) {
    ull r;
    asm("mov.b64 %0, {%1, %2};" : "=l"(r) : "f"(lo), "f"(hi));
    return r;
}
__device__ __forceinline__ float2 unpack2(ull v) {
    float2 f;
    asm("mov.b64 {%0, %1}, %2;" : "=f"(f.x), "=f"(f.y) : "l"(v));
    return f;
}

#define ABS2 0x7FFFFFFF7FFFFFFFULL

__global__ __launch_bounds__(TW, 2) void bsa_kernel(
    const float* __restrict__ grid,
    const float* __restrict__ guide,
    const float* __restrict__ inp,
    float* __restrict__ out)
{
    extern __shared__ __align__(16) float sm[];
    float*  gy  = sm;                                        // y-folded coeffs
    float*  sg  = sm + GY_FLOATS;                            // raw grid (temp)
    float4* bs4 = reinterpret_cast<float4*>(sm + GY_FLOATS); // basis (aliases sg)

    const int b  = blockIdx.z;
    const int w0 = blockIdx.x * TW;
    const int h0 = blockIdx.y * THR;
    const int t  = threadIdx.x;
    const float s = 15.0f / 511.0f;

    int ybase = (int)((float)h0 * s); if (ybase > GH - 2) ybase = GH - 2;
    int xbase = (int)((float)w0 * s); if (xbase > GW - 2) xbase = GW - 2;

    // ---- stage raw grid slice ----
    const float* gptr0 = grid + (size_t)b * (CO * 2 * DD * GH * GW);
    #pragma unroll
    for (int i = t; i < SG_FLOATS; i += TW) {
        int xx = i % NX;
        int r  = i / NX;
        int yy = r % NY;  r /= NY;
        int d  = r % DD;  r /= DD;
        int k  = r % 2;
        int co = r / 2;
        int gyy = ybase + yy; if (gyy > GH - 1) gyy = GH - 1;
        int gx  = xbase + xx; if (gx  > GW - 1) gx  = GW - 1;
        sg[(((yy * NX + xx) * 2 + k) * DD + d) * CO + co] =
            gptr0[(((co * 2 + k) * DD + d) * GH + gyy) * GW + gx];
    }
    __syncthreads();

    // ---- y-fold into gy; fold 1/16 into bias coeffs (mean/8 * basis 2x) ----
    #pragma unroll
    for (int j = t; j < THR * NX * DD * 16; j += TW) {
        int co = j & 7;
        int k  = (j >> 3) & 1;
        int d  = (j >> 4) & 7;
        int v  = j >> 7;           // r*NX + xx
        int xx = v % NX;
        int r  = v / NX;
        float yp = (float)(h0 + r) * s;
        int   y0 = (int)yp; if (y0 > GH - 2) y0 = GH - 2;
        float wy = yp - (float)y0;
        int   ly = y0 - ybase;
        float v0 = sg[(((ly       * NX + xx) * 2 + k) * DD + d) * CO + co];
        float v1 = sg[((((ly + 1) * NX + xx) * 2 + k) * DD + d) * CO + co];
        float val = v0 + wy * (v1 - v0);
        val *= (k ? 0.0625f : 1.0f);
        gy[(r * NX + xx) * CSTR + d * 16 + k * 8 + co] = val;
    }
    __syncthreads();   // y-fold reads sg; phase 1 overwrites it (bs4 alias)

    // ---- phase 1: dense f32x2 z-basis, registers -> one STS.128 per pair ----
    {
        const size_t hw = (size_t)HH * WW;
        const float* gup  = guide + (size_t)b * CI * hw + (size_t)h0 * WW + w0 + t;
        const float* inpp = inp   + (size_t)b * CI * hw + (size_t)h0 * WW + w0 + t;

        const ull NDC0 = pack2(-0.0f, -1.0f);
        const ull NDC1 = pack2(-2.0f, -3.0f);
        const ull NDC2 = pack2(-4.0f, -5.0f);
        const ull NDC3 = pack2(-6.0f, -7.0f);
        const ull ONE2  = pack2(1.0f, 1.0f);
        const ull NEG12 = pack2(-1.0f, -1.0f);

        #pragma unroll
        for (int r = 0; r < THR; r++) {
            ull A2[4] = {0ull, 0ull, 0ull, 0ull};
            ull B2[4] = {0ull, 0ull, 0ull, 0ull};

            #pragma unroll
            for (int ci = 0; ci < CI; ci++) {
                float g = gup [ci * hw + (size_t)r * WW];
                float v = inpp[ci * hw + (size_t)r * WW];
                float zp = fminf(fmaxf(g * 7.0f, 0.0f), 7.0f);
                ull zp2 = pack2(zp, zp);
                float vh = 0.5f * v;
                ull vh2 = pack2(vh, vh);
                const ull ndc[4] = {NDC0, NDC1, NDC2, NDC3};
                #pragma unroll
                for (int p = 0; p < 4; p++) {
                    ull tt = fadd2(zp2, ndc[p]);     // zp - d
                    tt &= ABS2;                       // |zp - d|
                    ull u  = ffma2(tt, NEG12, ONE2);  // 1 - |.|
                    ull au = u & ABS2;
                    ull w2 = fadd2(u, au);            // 2*relu(.)
                    A2[p] = ffma2(vh2, w2, A2[p]);    // (v/2)*2wd = v*wd
                    B2[p] = fadd2(B2[p], w2);         // 2*sum wd (1/16 in coeff)
                }
            }

            int px = r * TW + t;
            int ph = px + (px >> 3);                  // conflict-free pad
            #pragma unroll
            for (int p = 0; p < 4; p++) {
                float2 fa = unpack2(A2[p]);
                float2 fb = unpack2(B2[p]);
                bs4[p * PSTR + ph] = make_float4(fa.x, fa.y, fb.x, fb.y);
            }
        }
    }
    __syncthreads();

    // ---- phase 2: 4 px x 8 co per thread, 3-cell u-basis ----
    const int r    = t >> 6;
    const int gcol = (t & 63) << 2;   // start column within tile

    float u[3][4];
    int x00 = 0;
    #pragma unroll
    for (int j = 0; j < 4; j++) {
        float xp = (float)(w0 + gcol + j) * s;
        int   x0 = (int)xp; if (x0 > GW - 2) x0 = GW - 2;
        float wx = xp - (float)x0;
        if (j == 0) x00 = x0;
        int c = x0 - x00;             // 0 or 1
        u[0][j] = (c == 0) ? (1.0f - wx) : 0.0f;
        u[1][j] = (c == 0) ? wx          : (1.0f - wx);
        u[2][j] = (c == 0) ? 0.0f        : wx;
    }
    const int lx0 = x00 - xbase;
    const float* cell0 = gy + (r * NX + lx0) * CSTR;

    ull UU[3][4];
    #pragma unroll
    for (int c = 0; c < 3; c++)
        #pragma unroll
        for (int j = 0; j < 4; j++) UU[c][j] = pack2(u[c][j], u[c][j]);

    ull acc[4][4];
    #pragma unroll
    for (int j = 0; j < 4; j++)
        #pragma unroll
        for (int p = 0; p < 4; p++) acc[j][p] = 0ull;

    {
        int px0 = r * TW + gcol;
        int ph0 = px0 + (px0 >> 3);   // 4 px stay contiguous within 8-group

        #pragma unroll
        for (int p = 0; p < 4; p++) {
            const float4* q = bs4 + p * PSTR + ph0;
            float4 q0 = q[0], q1 = q[1], q2 = q[2], q3 = q[3];

            ull AU[2][4], BU[2][4];
            AU[0][0] = pack2(q0.x, q0.x); AU[1][0] = pack2(q0.y, q0.y);
            BU[0][0] = pack2(q0.z, q0.z); BU[1][0] = pack2(q0.w, q0.w);
            AU[0][1] = pack2(q1.x, q1.x); AU[1][1] = pack2(q1.y, q1.y);
            BU[0][1] = pack2(q1.z, q1.z); BU[1][1] = pack2(q1.w, q1.w);
            AU[0][2] = pack2(q2.x, q2.x); AU[1][2] = pack2(q2.y, q2.y);
            BU[0][2] = pack2(q2.z, q2.z); BU[1][2] = pack2(q2.w, q2.w);
            AU[0][3] = pack2(q3.x, q3.x); AU[1][3] = pack2(q3.y, q3.y);
            BU[0][3] = pack2(q3.z, q3.z); BU[1][3] = pack2(q3.w, q3.w);

            #pragma unroll
            for (int c = 0; c < 3; c++) {
                #pragma unroll
                for (int h = 0; h < 2; h++) {
                    const int d = 2 * p + h;
                    const ulonglong2* cp =
                        reinterpret_cast<const ulonglong2*>(cell0 + c * CSTR + d * 16);
                    ulonglong2 w01 = cp[0];   // W co0..3
                    ulonglong2 w23 = cp[1];   // W co4..7
                    ulonglong2 b01 = cp[2];   // B co0..3 (pre-scaled 1/16)
                    ulonglong2 b23 = cp[3];   // B co4..7
                    #pragma unroll
                    for (int j = 0; j < 4; j++) {
                        ull AUU = fmul2(AU[h][j], UU[c][j]);
                        ull BUU = fmul2(BU[h][j], UU[c][j]);
                        acc[j][0] = ffma2(w01.x, AUU, acc[j][0]);
                        acc[j][1] = ffma2(w01.y, AUU, acc[j][1]);
                        acc[j][2] = ffma2(w23.x, AUU, acc[j][2]);
                        acc[j][3] = ffma2(w23.y, AUU, acc[j][3]);
                        acc[j][0] = ffma2(b01.x, BUU, acc[j][0]);
                        acc[j][1] = ffma2(b01.y, BUU, acc[j][1]);
                        acc[j][2] = ffma2(b23.x, BUU, acc[j][2]);
                        acc[j][3] = ffma2(b23.y, BUU, acc[j][3]);
                    }
                }
            }
        }
    }

    // ---- epilogue: transpose to [co][4px], STG.128 per co ----
    const size_t hw = (size_t)HH * WW;
    float* op = out + (size_t)b * CO * hw + (size_t)(h0 + r) * WW + w0 + gcol;

    float vals[4][8];   // [px][co]
    #pragma unroll
    for (int j = 0; j < 4; j++) {
        #pragma unroll
        for (int p = 0; p < 4; p++) {
            float2 f = unpack2(acc[j][p]);
            vals[j][2 * p]     = f.x;
            vals[j][2 * p + 1] = f.y;
        }
    }
    #pragma unroll
    for (int co = 0; co < CO; co++) {
        float4 qv = make_float4(vals[0][co], vals[1][co], vals[2][co], vals[3][co]);
        *reinterpret_cast<float4*>(op + (size_t)co * hw) = qv;
    }
}

extern "C" void kernel_launch(void* const* d_in, const int* in_sizes, int n_in,
                              void* d_out, int out_size) {
    const float* grid  = (const float*)d_in[0];   // (2,8,2,8,16,16)
    const float* guide = (const float*)d_in[1];   // (2,8,512,512)
    const float* inp   = (const float*)d_in[2];   // (2,8,512,512)
    float* out = (float*)d_out;                   // (2,8,512,512)

    cudaFuncSetAttribute(bsa_kernel,
                         cudaFuncAttributeMaxDynamicSharedMemorySize, SMEM_BYTES);

    dim3 gdim(WW / TW, HH / THR, Bn);   // (2, 128, 2) = 512 blocks
    bsa_kernel<<<gdim, TW, SMEM_BYTES>>>(grid, guide, inp, out);
}

// round 8
// speedup vs baseline: 1.1175x; 1.0618x over previous
#include <cuda_runtime.h>
#include <cuda_fp16.h>

#define Bn  2
#define CO  8
#define CI  8
#define DD  8
#define GH  16
#define GW  16
#define HH  512
#define WW  512
#define TW  256        // threads per block = tile width in pixels
#define THR 4          // tile height (rows)
#define NY  3
#define NX  10
#define CSTR 132       // floats per (r,xx) cell in gy

#define PLANE 1024     // half2 elements per d-plane (1024 px)
#define GY_FLOATS   (THR * NX * CSTR)                  // 5280
#define SG_FLOATS   (NY * NX * 2 * DD * CO)            // 3840
#define SMEM_BYTES  (GY_FLOATS * 4 + DD * PLANE * 4)   // 21120 + 32768 = 53888

typedef unsigned long long ull;

__device__ __forceinline__ ull ffma2(ull a, ull b, ull c) {
    ull d;
    asm("fma.rn.f32x2 %0, %1, %2, %3;" : "=l"(d) : "l"(a), "l"(b), "l"(c));
    return d;
}
__device__ __forceinline__ ull fadd2(ull a, ull b) {
    ull d;
    asm("add.rn.f32x2 %0, %1, %2;" : "=l"(d) : "l"(a), "l"(b));
    return d;
}
__device__ __forceinline__ ull pack2(float lo, float hi) {
    ull r;
    asm("mov.b64 %0, {%1, %2};" : "=l"(r) : "f"(lo), "f"(hi));
    return r;
}
__device__ __forceinline__ float2 unpack2(ull v) {
    float2 f;
    asm("mov.b64 {%0, %1}, %2;" : "=f"(f.x), "=f"(f.y) : "l"(v));
    return f;
}

#define ABS2 0x7FFFFFFF7FFFFFFFULL

__global__ __launch_bounds__(TW, 3) void bsa_kernel(
    const float* __restrict__ grid,
    const float* __restrict__ guide,
    const float* __restrict__ inp,
    float* __restrict__ out)
{
    extern __shared__ __align__(16) float sm[];
    float*   gy  = sm;                                          // y-folded coeffs
    float*   sg  = sm + GY_FLOATS;                              // raw grid (temp)
    __half2* bsH = reinterpret_cast<__half2*>(sm + GY_FLOATS);  // basis (aliases sg)

    const int b  = blockIdx.z;
    const int w0 = blockIdx.x * TW;
    const int h0 = blockIdx.y * THR;
    const int t  = threadIdx.x;
    const float s = 15.0f / 511.0f;

    int ybase = (int)((float)h0 * s); if (ybase > GH - 2) ybase = GH - 2;
    int xbase = (int)((float)w0 * s); if (xbase > GW - 2) xbase = GW - 2;

    // ---- stage raw grid slice ----
    const float* gptr0 = grid + (size_t)b * (CO * 2 * DD * GH * GW);
    #pragma unroll
    for (int i = t; i < SG_FLOATS; i += TW) {
        int xx = i % NX;
        int r  = i / NX;
        int yy = r % NY;  r /= NY;
        int d  = r % DD;  r /= DD;
        int k  = r % 2;
        int co = r / 2;
        int gyy = ybase + yy; if (gyy > GH - 1) gyy = GH - 1;
        int gx  = xbase + xx; if (gx  > GW - 1) gx  = GW - 1;
        sg[(((yy * NX + xx) * 2 + k) * DD + d) * CO + co] =
            gptr0[(((co * 2 + k) * DD + d) * GH + gyy) * GW + gx];
    }
    __syncthreads();

    // ---- y-fold into gy; fold 1/16 into bias coeffs (mean/8 * basis 2x) ----
    #pragma unroll
    for (int j = t; j < THR * NX * DD * 16; j += TW) {
        int co = j & 7;
        int k  = (j >> 3) & 1;
        int d  = (j >> 4) & 7;
        int v  = j >> 7;           // r*NX + xx
        int xx = v % NX;
        int r  = v / NX;
        float yp = (float)(h0 + r) * s;
        int   y0 = (int)yp; if (y0 > GH - 2) y0 = GH - 2;
        float wy = yp - (float)y0;
        int   ly = y0 - ybase;
        float v0 = sg[(((ly       * NX + xx) * 2 + k) * DD + d) * CO + co];
        float v1 = sg[((((ly + 1) * NX + xx) * 2 + k) * DD + d) * CO + co];
        float val = v0 + wy * (v1 - v0);
        val *= (k ? 0.0625f : 1.0f);
        gy[(r * NX + xx) * CSTR + d * 16 + k * 8 + co] = val;
    }
    __syncthreads();   // y-fold reads sg; phase 1 overwrites it (bsH alias)

    // ---- phase 1: dense f32x2 z-basis in regs -> half2 (A,Bv) per (d,px) ----
    {
        const size_t hw = (size_t)HH * WW;
        const float* gup  = guide + (size_t)b * CI * hw + (size_t)h0 * WW + w0 + t;
        const float* inpp = inp   + (size_t)b * CI * hw + (size_t)h0 * WW + w0 + t;

        const ull ONE2  = pack2(1.0f, 1.0f);
        const ull NEG12 = pack2(-1.0f, -1.0f);

        #pragma unroll
        for (int r = 0; r < THR; r++) {
            ull A2[4] = {0ull, 0ull, 0ull, 0ull};
            ull B2[4] = {0ull, 0ull, 0ull, 0ull};

            #pragma unroll
            for (int ci = 0; ci < CI; ci++) {
                float g = gup [ci * hw + (size_t)r * WW];
                float v = inpp[ci * hw + (size_t)r * WW];
                float zp = fminf(fmaxf(g * 7.0f, 0.0f), 7.0f);
                ull zp2 = pack2(zp, zp);
                float vh = 0.5f * v;
                ull vh2 = pack2(vh, vh);
                #pragma unroll
                for (int p = 0; p < 4; p++) {
                    ull ndc = pack2(-(float)(2 * p), -(float)(2 * p + 1));
                    ull tt = fadd2(zp2, ndc);         // zp - d
                    tt &= ABS2;                       // |zp - d|
                    ull u  = ffma2(tt, NEG12, ONE2);  // 1 - |.|
                    ull au = u & ABS2;
                    ull w2 = fadd2(u, au);            // 2*relu(.)
                    A2[p] = ffma2(vh2, w2, A2[p]);    // (v/2)*2wd = v*wd
                    B2[p] = fadd2(B2[p], w2);         // 2*sum wd (1/16 in coeff)
                }
            }

            __half2* col = bsH + (r * TW + t);
            #pragma unroll
            for (int p = 0; p < 4; p++) {
                float2 fa = unpack2(A2[p]);
                float2 fb = unpack2(B2[p]);
                col[(2 * p)     * PLANE] = __floats2half2_rn(fa.x, fb.x);
                col[(2 * p + 1) * PLANE] = __floats2half2_rn(fa.y, fb.y);
            }
        }
    }
    __syncthreads();

    // ---- phase 2: 4 px x 8 co per thread, 3-cell u-basis ----
    const int r    = t >> 6;
    const int gcol = (t & 63) << 2;   // start column within tile

    float u[3][4];
    int x00 = 0;
    #pragma unroll
    for (int j = 0; j < 4; j++) {
        float xp = (float)(w0 + gcol + j) * s;
        int   x0 = (int)xp; if (x0 > GW - 2) x0 = GW - 2;
        float wx = xp - (float)x0;
        if (j == 0) x00 = x0;
        int c = x0 - x00;             // 0 or 1
        u[0][j] = (c == 0) ? (1.0f - wx) : 0.0f;
        u[1][j] = (c == 0) ? wx          : (1.0f - wx);
        u[2][j] = (c == 0) ? 0.0f        : wx;
    }
    const int lx0 = x00 - xbase;
    const float* cell0 = gy + (r * NX + lx0) * CSTR;

    ull acc[4][4];
    #pragma unroll
    for (int j = 0; j < 4; j++)
        #pragma unroll
        for (int p = 0; p < 4; p++) acc[j][p] = 0ull;

    const int px0 = r * TW + gcol;

    #pragma unroll
    for (int d = 0; d < DD; d++) {
        // one LDS.128 = 4 px of (A, Bv) in fp16
        float4 raw = *reinterpret_cast<const float4*>(bsH + d * PLANE + px0);
        const __half2* hp = reinterpret_cast<const __half2*>(&raw);
        float2 f0 = __half22float2(hp[0]);
        float2 f1 = __half22float2(hp[1]);
        float2 f2 = __half22float2(hp[2]);
        float2 f3 = __half22float2(hp[3]);
        float Aj[4] = {f0.x, f1.x, f2.x, f3.x};
        float Bj[4] = {f0.y, f1.y, f2.y, f3.y};

        #pragma unroll
        for (int c = 0; c < 3; c++) {
            const ulonglong2* cp =
                reinterpret_cast<const ulonglong2*>(cell0 + c * CSTR + d * 16);
            ulonglong2 w01 = cp[0];   // W co0..3
            ulonglong2 w23 = cp[1];   // W co4..7
            ulonglong2 b01 = cp[2];   // B co0..3 (pre-scaled 1/16)
            ulonglong2 b23 = cp[3];   // B co4..7
            #pragma unroll
            for (int j = 0; j < 4; j++) {
                float uu = u[c][j];
                float au = Aj[j] * uu;
                float bu = Bj[j] * uu;
                ull AU = pack2(au, au);
                ull BU = pack2(bu, bu);
                acc[j][0] = ffma2(w01.x, AU, acc[j][0]);
                acc[j][1] = ffma2(w01.y, AU, acc[j][1]);
                acc[j][2] = ffma2(w23.x, AU, acc[j][2]);
                acc[j][3] = ffma2(w23.y, AU, acc[j][3]);
                acc[j][0] = ffma2(b01.x, BU, acc[j][0]);
                acc[j][1] = ffma2(b01.y, BU, acc[j][1]);
                acc[j][2] = ffma2(b23.x, BU, acc[j][2]);
                acc[j][3] = ffma2(b23.y, BU, acc[j][3]);
            }
        }
    }

    // ---- epilogue: transpose to [co][4px], STG.128 per co ----
    const size_t hw = (size_t)HH * WW;
    float* op = out + (size_t)b * CO * hw + (size_t)(h0 + r) * WW + w0 + gcol;

    float vals[4][8];   // [px][co]
    #pragma unroll
    for (int j = 0; j < 4; j++) {
        #pragma unroll
        for (int p = 0; p < 4; p++) {
            float2 f = unpack2(acc[j][p]);
            vals[j][2 * p]     = f.x;
            vals[j][2 * p + 1] = f.y;
        }
    }
    #pragma unroll
    for (int co = 0; co < CO; co++) {
        float4 qv = make_float4(vals[0][co], vals[1][co], vals[2][co], vals[3][co]);
        *reinterpret_cast<float4*>(op + (size_t)co * hw) = qv;
    }
}

extern "C" void kernel_launch(void* const* d_in, const int* in_sizes, int n_in,
                              void* d_out, int out_size) {
    const float* grid  = (const float*)d_in[0];   // (2,8,2,8,16,16)
    const float* guide = (const float*)d_in[1];   // (2,8,512,512)
    const float* inp   = (const float*)d_in[2];   // (2,8,512,512)
    float* out = (float*)d_out;                   // (2,8,512,512)

    cudaFuncSetAttribute(bsa_kernel,
                         cudaFuncAttributeMaxDynamicSharedMemorySize, SMEM_BYTES);

    dim3 gdim(WW / TW, HH / THR, Bn);   // (2, 128, 2) = 512 blocks
    bsa_kernel<<<gdim, TW, SMEM_BYTES>>>(grid, guide, inp, out);
}

// round 9
// speedup vs baseline: 1.1430x; 1.0228x over previous
#include <cuda_runtime.h>
#include <cuda_fp16.h>

#define Bn  2
#define CO  8
#define CI  8
#define DD  8
#define GH  16
#define GW  16
#define HH  512
#define WW  512
#define TW  128        // threads per block = tile width in pixels
#define THR 4          // tile height (rows)
#define NY  3
#define NX  7          // x grid cols cached (lx0<=4, +2 cells, +corner)
#define CSTR 132       // floats per (r,xx) cell in gy

#define PLANE 512      // half2 elements per d-plane (512 px)
#define GY_FLOATS   (THR * NX * CSTR)                  // 3696
#define SG_FLOATS   (NY * NX * 2 * DD * CO)            // 2688
#define SMEM_BYTES  (GY_FLOATS * 4 + DD * PLANE * 4)   // 14784 + 16384 = 31168

typedef unsigned long long ull;

__device__ __forceinline__ ull ffma2(ull a, ull b, ull c) {
    ull d;
    asm("fma.rn.f32x2 %0, %1, %2, %3;" : "=l"(d) : "l"(a), "l"(b), "l"(c));
    return d;
}
__device__ __forceinline__ ull fadd2(ull a, ull b) {
    ull d;
    asm("add.rn.f32x2 %0, %1, %2;" : "=l"(d) : "l"(a), "l"(b));
    return d;
}
__device__ __forceinline__ ull pack2(float lo, float hi) {
    ull r;
    asm("mov.b64 %0, {%1, %2};" : "=l"(r) : "f"(lo), "f"(hi));
    return r;
}
__device__ __forceinline__ float2 unpack2(ull v) {
    float2 f;
    asm("mov.b64 {%0, %1}, %2;" : "=f"(f.x), "=f"(f.y) : "l"(v));
    return f;
}

#define ABS2 0x7FFFFFFF7FFFFFFFULL

__global__ __launch_bounds__(TW, 7) void bsa_kernel(
    const float* __restrict__ grid,
    const float* __restrict__ guide,
    const float* __restrict__ inp,
    float* __restrict__ out)
{
    extern __shared__ __align__(16) float sm[];
    float*   gy  = sm;                                          // y-folded coeffs
    float*   sg  = sm + GY_FLOATS;                              // raw grid (temp)
    __half2* bsH = reinterpret_cast<__half2*>(sm + GY_FLOATS);  // basis (aliases sg)

    const int b  = blockIdx.z;
    const int w0 = blockIdx.x * TW;
    const int h0 = blockIdx.y * THR;
    const int t  = threadIdx.x;
    const float s = 15.0f / 511.0f;

    int ybase = (int)((float)h0 * s); if (ybase > GH - 2) ybase = GH - 2;
    int xbase = (int)((float)w0 * s); if (xbase > GW - 2) xbase = GW - 2;

    // ---- stage raw grid slice ----
    const float* gptr0 = grid + (size_t)b * (CO * 2 * DD * GH * GW);
    #pragma unroll
    for (int i = t; i < SG_FLOATS; i += TW) {
        int xx = i % NX;
        int r  = i / NX;
        int yy = r % NY;  r /= NY;
        int d  = r % DD;  r /= DD;
        int k  = r % 2;
        int co = r / 2;
        int gyy = ybase + yy; if (gyy > GH - 1) gyy = GH - 1;
        int gx  = xbase + xx; if (gx  > GW - 1) gx  = GW - 1;
        sg[(((yy * NX + xx) * 2 + k) * DD + d) * CO + co] =
            gptr0[(((co * 2 + k) * DD + d) * GH + gyy) * GW + gx];
    }
    __syncthreads();

    // ---- y-fold into gy; fold 1/16 into bias coeffs (mean/8 * basis 2x) ----
    #pragma unroll
    for (int j = t; j < THR * NX * DD * 16; j += TW) {
        int co = j & 7;
        int k  = (j >> 3) & 1;
        int d  = (j >> 4) & 7;
        int v  = j >> 7;           // r*NX + xx
        int xx = v % NX;
        int r  = v / NX;
        float yp = (float)(h0 + r) * s;
        int   y0 = (int)yp; if (y0 > GH - 2) y0 = GH - 2;
        float wy = yp - (float)y0;
        int   ly = y0 - ybase;
        float v0 = sg[(((ly       * NX + xx) * 2 + k) * DD + d) * CO + co];
        float v1 = sg[((((ly + 1) * NX + xx) * 2 + k) * DD + d) * CO + co];
        float val = v0 + wy * (v1 - v0);
        val *= (k ? 0.0625f : 1.0f);
        gy[(r * NX + xx) * CSTR + d * 16 + k * 8 + co] = val;
    }
    __syncthreads();   // y-fold reads sg; phase 1 overwrites it (bsH alias)

    // ---- phase 1: dense f32x2 z-basis in regs -> half2 (A,Bv) per (d,px) ----
    {
        const size_t hw = (size_t)HH * WW;
        const float* gup  = guide + (size_t)b * CI * hw + (size_t)h0 * WW + w0 + t;
        const float* inpp = inp   + (size_t)b * CI * hw + (size_t)h0 * WW + w0 + t;

        const ull ONE2  = pack2(1.0f, 1.0f);
        const ull NEG12 = pack2(-1.0f, -1.0f);

        #pragma unroll
        for (int r = 0; r < THR; r++) {
            ull A2[4] = {0ull, 0ull, 0ull, 0ull};
            ull B2[4] = {0ull, 0ull, 0ull, 0ull};

            #pragma unroll
            for (int ci = 0; ci < CI; ci++) {
                float g = gup [ci * hw + (size_t)r * WW];
                float v = inpp[ci * hw + (size_t)r * WW];
                float zp = fminf(fmaxf(g * 7.0f, 0.0f), 7.0f);
                ull zp2 = pack2(zp, zp);
                float vh = 0.5f * v;
                ull vh2 = pack2(vh, vh);
                #pragma unroll
                for (int p = 0; p < 4; p++) {
                    ull ndc = pack2(-(float)(2 * p), -(float)(2 * p + 1));
                    ull tt = fadd2(zp2, ndc);         // zp - d
                    tt &= ABS2;                       // |zp - d|
                    ull u  = ffma2(tt, NEG12, ONE2);  // 1 - |.|
                    ull au = u & ABS2;
                    ull w2 = fadd2(u, au);            // 2*relu(.)
                    A2[p] = ffma2(vh2, w2, A2[p]);    // (v/2)*2wd = v*wd
                    B2[p] = fadd2(B2[p], w2);         // 2*sum wd (1/16 in coeff)
                }
            }

            __half2* col = bsH + (r * TW + t);
            #pragma unroll
            for (int p = 0; p < 4; p++) {
                float2 fa = unpack2(A2[p]);
                float2 fb = unpack2(B2[p]);
                col[(2 * p)     * PLANE] = __floats2half2_rn(fa.x, fb.x);
                col[(2 * p + 1) * PLANE] = __floats2half2_rn(fa.y, fb.y);
            }
        }
    }
    __syncthreads();

    // ---- phase 2: 4 px x 8 co per thread, 3-cell u-basis ----
    const int r    = t >> 5;          // row within tile
    const int gcol = (t & 31) << 2;   // start column within tile

    float u[3][4];
    int x00 = 0;
    #pragma unroll
    for (int j = 0; j < 4; j++) {
        float xp = (float)(w0 + gcol + j) * s;
        int   x0 = (int)xp; if (x0 > GW - 2) x0 = GW - 2;
        float wx = xp - (float)x0;
        if (j == 0) x00 = x0;
        int c = x0 - x00;             // 0 or 1
        u[0][j] = (c == 0) ? (1.0f - wx) : 0.0f;
        u[1][j] = (c == 0) ? wx          : (1.0f - wx);
        u[2][j] = (c == 0) ? 0.0f        : wx;
    }
    const int lx0 = x00 - xbase;
    const float* cell0 = gy + (r * NX + lx0) * CSTR;

    ull acc[4][4];
    #pragma unroll
    for (int j = 0; j < 4; j++)
        #pragma unroll
        for (int p = 0; p < 4; p++) acc[j][p] = 0ull;

    const int px0 = r * TW + gcol;

    #pragma unroll
    for (int d = 0; d < DD; d++) {
        // one LDS.128 = 4 px of (A, Bv) in fp16
        float4 raw = *reinterpret_cast<const float4*>(bsH + d * PLANE + px0);
        const __half2* hp = reinterpret_cast<const __half2*>(&raw);
        float2 f0 = __half22float2(hp[0]);
        float2 f1 = __half22float2(hp[1]);
        float2 f2 = __half22float2(hp[2]);
        float2 f3 = __half22float2(hp[3]);
        float Aj[4] = {f0.x, f1.x, f2.x, f3.x};
        float Bj[4] = {f0.y, f1.y, f2.y, f3.y};

        #pragma unroll
        for (int c = 0; c < 3; c++) {
            const ulonglong2* cp =
                reinterpret_cast<const ulonglong2*>(cell0 + c * CSTR + d * 16);
            ulonglong2 w01 = cp[0];   // W co0..3
            ulonglong2 w23 = cp[1];   // W co4..7
            ulonglong2 b01 = cp[2];   // B co0..3 (pre-scaled 1/16)
            ulonglong2 b23 = cp[3];   // B co4..7
            #pragma unroll
            for (int j = 0; j < 4; j++) {
                float uu = u[c][j];
                float au = Aj[j] * uu;
                float bu = Bj[j] * uu;
                ull AU = pack2(au, au);
                ull BU = pack2(bu, bu);
                acc[j][0] = ffma2(w01.x, AU, acc[j][0]);
                acc[j][1] = ffma2(w01.y, AU, acc[j][1]);
                acc[j][2] = ffma2(w23.x, AU, acc[j][2]);
                acc[j][3] = ffma2(w23.y, AU, acc[j][3]);
                acc[j][0] = ffma2(b01.x, BU, acc[j][0]);
                acc[j][1] = ffma2(b01.y, BU, acc[j][1]);
                acc[j][2] = ffma2(b23.x, BU, acc[j][2]);
                acc[j][3] = ffma2(b23.y, BU, acc[j][3]);
            }
        }
    }

    // ---- epilogue: transpose to [co][4px], STG.128 per co ----
    const size_t hw = (size_t)HH * WW;
    float* op = out + (size_t)b * CO * hw + (size_t)(h0 + r) * WW + w0 + gcol;

    float vals[4][8];   // [px][co]
    #pragma unroll
    for (int j = 0; j < 4; j++) {
        #pragma unroll
        for (int p = 0; p < 4; p++) {
            float2 f = unpack2(acc[j][p]);
            vals[j][2 * p]     = f.x;
            vals[j][2 * p + 1] = f.y;
        }
    }
    #pragma unroll
    for (int co = 0; co < CO; co++) {
        float4 qv = make_float4(vals[0][co], vals[1][co], vals[2][co], vals[3][co]);
        *reinterpret_cast<float4*>(op + (size_t)co * hw) = qv;
    }
}

extern "C" void kernel_launch(void* const* d_in, const int* in_sizes, int n_in,
                              void* d_out, int out_size) {
    const float* grid  = (const float*)d_in[0];   // (2,8,2,8,16,16)
    const float* guide = (const float*)d_in[1];   // (2,8,512,512)
    const float* inp   = (const float*)d_in[2];   // (2,8,512,512)
    float* out = (float*)d_out;                   // (2,8,512,512)

    cudaFuncSetAttribute(bsa_kernel,
                         cudaFuncAttributeMaxDynamicSharedMemorySize, SMEM_BYTES);

    dim3 gdim(WW / TW, HH / THR, Bn);   // (4, 128, 2) = 1024 blocks
    bsa_kernel<<<gdim, TW, SMEM_BYTES>>>(grid, guide, inp, out);
}

// round 10
// speedup vs baseline: 1.3944x; 1.2200x over previous
#include <cuda_runtime.h>
#include <cuda_fp16.h>

#define Bn  2
#define CO  8
#define CI  8
#define DD  8
#define GH  16
#define GW  16
#define HH  512
#define WW  512
#define TW  128        // threads per block = tile width in pixels
#define THR 4          // tile height (rows)
#define NY  3
#define NX  7
#define XSTR 516       // floats per xx block in gy (4*128 + 4 pad)

#define GY_FLOATS   (NX * XSTR)                        // 3612
#define SG_FLOATS   (128 * 21)                         // 2688 (combo-major)
#define PLANE 512                                      // half2 per d-plane
#define BS_BYTES    (DD * PLANE * 4)                   // 16384
#define SMEM_BYTES  (GY_FLOATS * 4 + BS_BYTES)         // 14448 + 16384 = 30832

typedef unsigned long long ull;

__device__ __forceinline__ ull ffma2(ull a, ull b, ull c) {
    ull d;
    asm("fma.rn.f32x2 %0, %1, %2, %3;" : "=l"(d) : "l"(a), "l"(b), "l"(c));
    return d;
}
__device__ __forceinline__ ull fadd2(ull a, ull b) {
    ull d;
    asm("add.rn.f32x2 %0, %1, %2;" : "=l"(d) : "l"(a), "l"(b));
    return d;
}
__device__ __forceinline__ ull pack2(float lo, float hi) {
    ull r;
    asm("mov.b64 %0, {%1, %2};" : "=l"(r) : "f"(lo), "f"(hi));
    return r;
}
__device__ __forceinline__ float2 unpack2(ull v) {
    float2 f;
    asm("mov.b64 {%0, %1}, %2;" : "=f"(f.x), "=f"(f.y) : "l"(v));
    return f;
}

#define ABS2 0x7FFFFFFF7FFFFFFFULL

__global__ __launch_bounds__(TW, 7) void bsa_kernel(
    const float* __restrict__ grid,
    const float* __restrict__ guide,
    const float* __restrict__ inp,
    float* __restrict__ out)
{
    extern __shared__ __align__(16) float sm[];
    float*   gy  = sm;                                          // y-folded coeffs
    float*   sg  = sm + GY_FLOATS;                              // raw grid (temp)
    __half2* bsH = reinterpret_cast<__half2*>(sm + GY_FLOATS);  // basis (aliases sg)

    const int b  = blockIdx.z;
    const int w0 = blockIdx.x * TW;
    const int h0 = blockIdx.y * THR;
    const int t  = threadIdx.x;
    const float s = 15.0f / 511.0f;

    int ybase = (int)((float)h0 * s); if (ybase > GH - 2) ybase = GH - 2;
    int xbase = (int)((float)w0 * s); if (xbase > GW - 2) xbase = GW - 2;

    // ---- stage raw grid slice: sg[combo(d,k,co)][yy*7+xx] ----
    // loop index i = t + 128*m over [0,2688): xx = i%7, rr = i/7,
    // yy = rr>>7, cg = rr&127 where cg = co*16 + k*8 + d (gmem combo order).
    {
        const float* gptr0 = grid + (size_t)b * (CO * 2 * DD * GH * GW);
        int xx = t % 7;
        int rr = t / 7;
        #pragma unroll
        for (int m = 0; m < 21; m++) {
            int yy = rr >> 7;
            int cg = rr & 127;
            int gyy = ybase + yy; if (gyy > GH - 1) gyy = GH - 1;
            int gx  = xbase + xx; if (gx  > GW - 1) gx  = GW - 1;
            float val = gptr0[cg * 256 + gyy * 16 + gx];
            // storage combo index = d*16 + k*8 + co (swap co<->d fields)
            int ts = ((cg & 7) << 4) | (cg & 8) | (cg >> 4);
            sg[ts * 21 + yy * 7 + xx] = val;
            xx += 2; rr += 18;
            if (xx >= 7) { xx -= 7; rr += 1; }
        }
    }
    __syncthreads();

    // ---- y-fold: thread t owns combo t = d*16+k*8+co; all (r,xx) compile-time ----
    {
        const float* col = sg + t * 21;
        const float* rp[THR];
        float wyr[THR];
        #pragma unroll
        for (int r = 0; r < THR; r++) {
            float yp = (float)(h0 + r) * s;
            int   y0 = (int)yp; if (y0 > GH - 2) y0 = GH - 2;
            wyr[r] = yp - (float)y0;
            rp[r]  = col + (y0 - ybase) * 7;
        }
        float* gyt = gy + t;
        #pragma unroll
        for (int xx = 0; xx < NX; xx++) {
            #pragma unroll
            for (int r = 0; r < THR; r++) {
                float v0 = rp[r][xx];
                float v1 = rp[r][xx + 7];
                gyt[xx * XSTR + r * 128] = v0 + wyr[r] * (v1 - v0);
            }
        }
    }
    __syncthreads();   // y-fold reads sg; phase 1 overwrites it (bsH alias)

    // ---- phase 1: dense f32x2 z-basis in regs -> half2 (A,Bv/8) per (d,px) ----
    {
        const size_t hw = (size_t)HH * WW;
        const float* gup  = guide + (size_t)b * CI * hw + (size_t)h0 * WW + w0 + t;
        const float* inpp = inp   + (size_t)b * CI * hw + (size_t)h0 * WW + w0 + t;

        const ull ONE2  = pack2(1.0f, 1.0f);
        const ull NEG12 = pack2(-1.0f, -1.0f);
        const ull S16   = pack2(0.0625f, 0.0625f);   // (1/8 mean) * (1/2 for 2*wd)

        #pragma unroll
        for (int r = 0; r < THR; r++) {
            ull A2[4] = {0ull, 0ull, 0ull, 0ull};
            ull B2[4] = {0ull, 0ull, 0ull, 0ull};

            #pragma unroll
            for (int ci = 0; ci < CI; ci++) {
                float g = gup [ci * hw + (size_t)r * WW];
                float v = inpp[ci * hw + (size_t)r * WW];
                float zp = g * 7.0f;          // guide in [0,1) -> zp in [0,7)
                ull zp2 = pack2(zp, zp);
                float vh = 0.5f * v;
                ull vh2 = pack2(vh, vh);
                #pragma unroll
                for (int p = 0; p < 4; p++) {
                    ull ndc = pack2(-(float)(2 * p), -(float)(2 * p + 1));
                    ull tt = fadd2(zp2, ndc);         // zp - d
                    tt &= ABS2;                       // |zp - d|
                    ull u  = ffma2(tt, NEG12, ONE2);  // 1 - |.|
                    ull au = u & ABS2;
                    ull w2 = fadd2(u, au);            // 2*relu(.)
                    A2[p] = ffma2(vh2, w2, A2[p]);    // (v/2)*2wd = v*wd
                    B2[p] = ffma2(S16, w2, B2[p]);    // sum wd / 8
                }
            }

            __half2* col = bsH + (r * TW + t);
            #pragma unroll
            for (int p = 0; p < 4; p++) {
                float2 fa = unpack2(A2[p]);
                float2 fb = unpack2(B2[p]);
                col[(2 * p)     * PLANE] = __floats2half2_rn(fa.x, fb.x);
                col[(2 * p + 1) * PLANE] = __floats2half2_rn(fa.y, fb.y);
            }
        }
    }
    __syncthreads();

    // ---- phase 2: 4 px x 8 co per thread, 3-cell u-basis ----
    const int r    = t >> 5;          // row within tile (uniform per warp)
    const int gcol = (t & 31) << 2;   // start column within tile

    float u[3][4];
    int x00 = 0;
    #pragma unroll
    for (int j = 0; j < 4; j++) {
        float xp = (float)(w0 + gcol + j) * s;
        int   x0 = (int)xp; if (x0 > GW - 2) x0 = GW - 2;
        float wx = xp - (float)x0;
        if (j == 0) x00 = x0;
        int c = x0 - x00;             // 0 or 1
        u[0][j] = (c == 0) ? (1.0f - wx) : 0.0f;
        u[1][j] = (c == 0) ? wx          : (1.0f - wx);
        u[2][j] = (c == 0) ? 0.0f        : wx;
    }
    const int lx0 = x00 - xbase;
    const float* cell0 = gy + lx0 * XSTR + r * 128;

    ull acc[4][4];
    #pragma unroll
    for (int j = 0; j < 4; j++)
        #pragma unroll
        for (int p = 0; p < 4; p++) acc[j][p] = 0ull;

    const int px0 = r * TW + gcol;

    #pragma unroll
    for (int d = 0; d < DD; d++) {
        // one LDS.128 = 4 px of (A, Bv) in fp16
        float4 raw = *reinterpret_cast<const float4*>(bsH + d * PLANE + px0);
        const __half2* hp = reinterpret_cast<const __half2*>(&raw);
        float2 f0 = __half22float2(hp[0]);
        float2 f1 = __half22float2(hp[1]);
        float2 f2 = __half22float2(hp[2]);
        float2 f3 = __half22float2(hp[3]);
        float Aj[4] = {f0.x, f1.x, f2.x, f3.x};
        float Bj[4] = {f0.y, f1.y, f2.y, f3.y};

        #pragma unroll
        for (int c = 0; c < 3; c++) {
            const ulonglong2* cp =
                reinterpret_cast<const ulonglong2*>(cell0 + c * XSTR + d * 16);
            ulonglong2 w01 = cp[0];   // W co0..3
            ulonglong2 w23 = cp[1];   // W co4..7
            ulonglong2 b01 = cp[2];   // B co0..3
            ulonglong2 b23 = cp[3];   // B co4..7
            #pragma unroll
            for (int j = 0; j < 4; j++) {
                float uu = u[c][j];
                float au = Aj[j] * uu;
                float bu = Bj[j] * uu;
                ull AU = pack2(au, au);
                ull BU = pack2(bu, bu);
                acc[j][0] = ffma2(w01.x, AU, acc[j][0]);
                acc[j][1] = ffma2(w01.y, AU, acc[j][1]);
                acc[j][2] = ffma2(w23.x, AU, acc[j][2]);
                acc[j][3] = ffma2(w23.y, AU, acc[j][3]);
                acc[j][0] = ffma2(b01.x, BU, acc[j][0]);
                acc[j][1] = ffma2(b01.y, BU, acc[j][1]);
                acc[j][2] = ffma2(b23.x, BU, acc[j][2]);
                acc[j][3] = ffma2(b23.y, BU, acc[j][3]);
            }
        }
    }

    // ---- epilogue: transpose to [co][4px], STG.128 per co ----
    const size_t hw = (size_t)HH * WW;
    float* op = out + (size_t)b * CO * hw + (size_t)(h0 + r) * WW + w0 + gcol;

    float vals[4][8];   // [px][co]
    #pragma unroll
    for (int j = 0; j < 4; j++) {
        #pragma unroll
        for (int p = 0; p < 4; p++) {
            float2 f = unpack2(acc[j][p]);
            vals[j][2 * p]     = f.x;
            vals[j][2 * p + 1] = f.y;
        }
    }
    #pragma unroll
    for (int co = 0; co < CO; co++) {
        float4 qv = make_float4(vals[0][co], vals[1][co], vals[2][co], vals[3][co]);
        *reinterpret_cast<float4*>(op + (size_t)co * hw) = qv;
    }
}

extern "C" void kernel_launch(void* const* d_in, const int* in_sizes, int n_in,
                              void* d_out, int out_size) {
    const float* grid  = (const float*)d_in[0];   // (2,8,2,8,16,16)
    const float* guide = (const float*)d_in[1];   // (2,8,512,512)
    const float* inp   = (const float*)d_in[2];   // (2,8,512,512)
    float* out = (float*)d_out;                   // (2,8,512,512)

    cudaFuncSetAttribute(bsa_kernel,
                         cudaFuncAttributeMaxDynamicSharedMemorySize, SMEM_BYTES);

    dim3 gdim(WW / TW, HH / THR, Bn);   // (4, 128, 2) = 1024 blocks
    bsa_kernel<<<gdim, TW, SMEM_BYTES>>>(grid, guide, inp, out);
}

// round 11
// speedup vs baseline: 1.4087x; 1.0102x over previous
#include <cuda_runtime.h>
#include <cuda_fp16.h>

#define Bn  2
#define CO  8
#define CI  8
#define DD  8
#define GH  16
#define GW  16
#define HH  512
#define WW  512
#define TW  128        // threads per block = tile width in pixels
#define THR 4          // tile height (rows)
#define NY  3
#define NX  7
#define XSTR 516       // floats per xx block in gy (4*128 + 4 pad)

#define GY_FLOATS   (NX * XSTR)                        // 3612
#define SG_FLOATS   (128 * 21)                         // 2688 (combo-major)
#define PLANE 512                                      // half2 per d-plane
#define BS_BYTES    (DD * PLANE * 4)                   // 16384
#define SMEM_BYTES  (GY_FLOATS * 4 + BS_BYTES)         // 14448 + 16384 = 30832

typedef unsigned long long ull;

__device__ __forceinline__ ull ffma2(ull a, ull b, ull c) {
    ull d;
    asm("fma.rn.f32x2 %0, %1, %2, %3;" : "=l"(d) : "l"(a), "l"(b), "l"(c));
    return d;
}
__device__ __forceinline__ ull fadd2(ull a, ull b) {
    ull d;
    asm("add.rn.f32x2 %0, %1, %2;" : "=l"(d) : "l"(a), "l"(b));
    return d;
}
__device__ __forceinline__ ull pack2(float lo, float hi) {
    ull r;
    asm("mov.b64 %0, {%1, %2};" : "=l"(r) : "f"(lo), "f"(hi));
    return r;
}
__device__ __forceinline__ float2 unpack2(ull v) {
    float2 f;
    asm("mov.b64 {%0, %1}, %2;" : "=f"(f.x), "=f"(f.y) : "l"(v));
    return f;
}

#define ABS2 0x7FFFFFFF7FFFFFFFULL

__global__ __launch_bounds__(TW, 7) void bsa_kernel(
    const float* __restrict__ grid,
    const float* __restrict__ guide,
    const float* __restrict__ inp,
    float* __restrict__ out)
{
    extern __shared__ __align__(16) float sm[];
    float*   gy  = sm;                                          // y-folded coeffs
    float*   sg  = sm + GY_FLOATS;                              // raw grid (temp)
    __half2* bsH = reinterpret_cast<__half2*>(sm + GY_FLOATS);  // basis (aliases sg)

    const int b  = blockIdx.z;
    const int w0 = blockIdx.x * TW;
    const int h0 = blockIdx.y * THR;
    const int t  = threadIdx.x;
    const float s = 15.0f / 511.0f;

    int ybase = (int)((float)h0 * s); if (ybase > GH - 2) ybase = GH - 2;
    int xbase = (int)((float)w0 * s); if (xbase > GW - 2) xbase = GW - 2;

    // ---- stage raw grid slice: sg[combo(d,k,co)][yy*7+xx] ----
    // loop index i = t + 128*m over [0,2688): xx = i%7, rr = i/7,
    // yy = rr>>7, cg = rr&127 where cg = co*16 + k*8 + d (gmem combo order).
    {
        const float* gptr0 = grid + (size_t)b * (CO * 2 * DD * GH * GW);
        int xx = t % 7;
        int rr = t / 7;
        #pragma unroll
        for (int m = 0; m < 21; m++) {
            int yy = rr >> 7;
            int cg = rr & 127;
            int gyy = ybase + yy; if (gyy > GH - 1) gyy = GH - 1;
            int gx  = xbase + xx; if (gx  > GW - 1) gx  = GW - 1;
            float val = gptr0[cg * 256 + gyy * 16 + gx];
            // storage combo index = d*16 + k*8 + co (swap co<->d fields)
            int ts = ((cg & 7) << 4) | (cg & 8) | (cg >> 4);
            sg[ts * 21 + yy * 7 + xx] = val;
            xx += 2; rr += 18;
            if (xx >= 7) { xx -= 7; rr += 1; }
        }
    }
    __syncthreads();

    // ---- y-fold: thread t owns combo t = d*16+k*8+co; all (r,xx) compile-time ----
    {
        const float* col = sg + t * 21;
        const float* rp[THR];
        float wyr[THR];
        #pragma unroll
        for (int r = 0; r < THR; r++) {
            float yp = (float)(h0 + r) * s;
            int   y0 = (int)yp; if (y0 > GH - 2) y0 = GH - 2;
            wyr[r] = yp - (float)y0;
            rp[r]  = col + (y0 - ybase) * 7;
        }
        float* gyt = gy + t;
        #pragma unroll
        for (int xx = 0; xx < NX; xx++) {
            #pragma unroll
            for (int r = 0; r < THR; r++) {
                float v0 = rp[r][xx];
                float v1 = rp[r][xx + 7];
                gyt[xx * XSTR + r * 128] = v0 + wyr[r] * (v1 - v0);
            }
        }
    }
    __syncthreads();   // y-fold reads sg; phase 1 overwrites it (bsH alias)

    // ---- phase 1: dense f32x2 z-basis in regs -> half2 (A,Bv/8) per (d,px) ----
    {
        const size_t hw = (size_t)HH * WW;
        const float* gup  = guide + (size_t)b * CI * hw + (size_t)h0 * WW + w0 + t;
        const float* inpp = inp   + (size_t)b * CI * hw + (size_t)h0 * WW + w0 + t;

        const ull ONE2  = pack2(1.0f, 1.0f);
        const ull NEG12 = pack2(-1.0f, -1.0f);
        const ull S16   = pack2(0.0625f, 0.0625f);   // (1/8 mean) * (1/2 for 2*wd)

        #pragma unroll
        for (int r = 0; r < THR; r++) {
            ull A2[4] = {0ull, 0ull, 0ull, 0ull};
            ull B2[4] = {0ull, 0ull, 0ull, 0ull};

            #pragma unroll
            for (int ci = 0; ci < CI; ci++) {
                float g = gup [ci * hw + (size_t)r * WW];
                float v = inpp[ci * hw + (size_t)r * WW];
                float zp = g * 7.0f;          // guide in [0,1) -> zp in [0,7)
                ull zp2 = pack2(zp, zp);
                float vh = 0.5f * v;
                ull vh2 = pack2(vh, vh);
                #pragma unroll
                for (int p = 0; p < 4; p++) {
                    ull ndc = pack2(-(float)(2 * p), -(float)(2 * p + 1));
                    ull tt = fadd2(zp2, ndc);         // zp - d
                    tt &= ABS2;                       // |zp - d|
                    ull u  = ffma2(tt, NEG12, ONE2);  // 1 - |.|
                    ull au = u & ABS2;
                    ull w2 = fadd2(u, au);            // 2*relu(.)
                    A2[p] = ffma2(vh2, w2, A2[p]);    // (v/2)*2wd = v*wd
                    B2[p] = ffma2(S16, w2, B2[p]);    // sum wd / 8
                }
            }

            __half2* col = bsH + (r * TW + t);
            #pragma unroll
            for (int p = 0; p < 4; p++) {
                float2 fa = unpack2(A2[p]);
                float2 fb = unpack2(B2[p]);
                col[(2 * p)     * PLANE] = __floats2half2_rn(fa.x, fb.x);
                col[(2 * p + 1) * PLANE] = __floats2half2_rn(fa.y, fb.y);
            }
        }
    }
    __syncthreads();

    // ---- phase 2: 4 px x 8 co per thread, 3-cell u-basis ----
    const int r    = t >> 5;          // row within tile (uniform per warp)
    const int gcol = (t & 31) << 2;   // start column within tile

    float u[3][4];
    int x00 = 0;
    #pragma unroll
    for (int j = 0; j < 4; j++) {
        float xp = (float)(w0 + gcol + j) * s;
        int   x0 = (int)xp; if (x0 > GW - 2) x0 = GW - 2;
        float wx = xp - (float)x0;
        if (j == 0) x00 = x0;
        int c = x0 - x00;             // 0 or 1
        u[0][j] = (c == 0) ? (1.0f - wx) : 0.0f;
        u[1][j] = (c == 0) ? wx          : (1.0f - wx);
        u[2][j] = (c == 0) ? 0.0f        : wx;
    }
    const int lx0 = x00 - xbase;
    const float* cell0 = gy + lx0 * XSTR + r * 128;

    ull acc[4][4];
    #pragma unroll
    for (int j = 0; j < 4; j++)
        #pragma unroll
        for (int p = 0; p < 4; p++) acc[j][p] = 0ull;

    const int px0 = r * TW + gcol;

    #pragma unroll
    for (int d = 0; d < DD; d++) {
        // one LDS.128 = 4 px of (A, Bv) in fp16
        float4 raw = *reinterpret_cast<const float4*>(bsH + d * PLANE + px0);
        const __half2* hp = reinterpret_cast<const __half2*>(&raw);
        float2 f0 = __half22float2(hp[0]);
        float2 f1 = __half22float2(hp[1]);
        float2 f2 = __half22float2(hp[2]);
        float2 f3 = __half22float2(hp[3]);
        float Aj[4] = {f0.x, f1.x, f2.x, f3.x};
        float Bj[4] = {f0.y, f1.y, f2.y, f3.y};

        #pragma unroll
        for (int c = 0; c < 3; c++) {
            const ulonglong2* cp =
                reinterpret_cast<const ulonglong2*>(cell0 + c * XSTR + d * 16);
            ulonglong2 w01 = cp[0];   // W co0..3
            ulonglong2 w23 = cp[1];   // W co4..7
            ulonglong2 b01 = cp[2];   // B co0..3
            ulonglong2 b23 = cp[3];   // B co4..7
            #pragma unroll
            for (int j = 0; j < 4; j++) {
                float uu = u[c][j];
                float au = Aj[j] * uu;
                float bu = Bj[j] * uu;
                ull AU = pack2(au, au);
                ull BU = pack2(bu, bu);
                acc[j][0] = ffma2(w01.x, AU, acc[j][0]);
                acc[j][1] = ffma2(w01.y, AU, acc[j][1]);
                acc[j][2] = ffma2(w23.x, AU, acc[j][2]);
                acc[j][3] = ffma2(w23.y, AU, acc[j][3]);
                acc[j][0] = ffma2(b01.x, BU, acc[j][0]);
                acc[j][1] = ffma2(b01.y, BU, acc[j][1]);
                acc[j][2] = ffma2(b23.x, BU, acc[j][2]);
                acc[j][3] = ffma2(b23.y, BU, acc[j][3]);
            }
        }
    }

    // ---- epilogue: transpose to [co][4px], STG.128 per co ----
    const size_t hw = (size_t)HH * WW;
    float* op = out + (size_t)b * CO * hw + (size_t)(h0 + r) * WW + w0 + gcol;

    float vals[4][8];   // [px][co]
    #pragma unroll
    for (int j = 0; j < 4; j++) {
        #pragma unroll
        for (int p = 0; p < 4; p++) {
            float2 f = unpack2(acc[j][p]);
            vals[j][2 * p]     = f.x;
            vals[j][2 * p + 1] = f.y;
        }
    }
    #pragma unroll
    for (int co = 0; co < CO; co++) {
        float4 qv = make_float4(vals[0][co], vals[1][co], vals[2][co], vals[3][co]);
        *reinterpret_cast<float4*>(op + (size_t)co * hw) = qv;
    }
}

extern "C" void kernel_launch(void* const* d_in, const int* in_sizes, int n_in,
                              void* d_out, int out_size) {
    const float* grid  = (const float*)d_in[0];   // (2,8,2,8,16,16)
    const float* guide = (const float*)d_in[1];   // (2,8,512,512)
    const float* inp   = (const float*)d_in[2];   // (2,8,512,512)
    float* out = (float*)d_out;                   // (2,8,512,512)

    cudaFuncSetAttribute(bsa_kernel,
                         cudaFuncAttributeMaxDynamicSharedMemorySize, SMEM_BYTES);

    dim3 gdim(WW / TW, HH / THR, Bn);   // (4, 128, 2) = 1024 blocks
    bsa_kernel<<<gdim, TW, SMEM_BYTES>>>(grid, guide, inp, out);
}